// round 2
// baseline (speedup 1.0000x reference)
#include <cuda_runtime.h>
#include <cuda_bf16.h>
#include <cstdint>
#include <cfloat>

// ---------------------------------------------------------------------------
// VectorQuantize forward (eval): argmin_k ||x - e_k||^2, gather, straight-
// through z_q_st, commitment loss, indices.
//
//   z_e   : [B=32, D=64, H=64, W=64] f32
//   embed : [K=1024, D=64] f32
// Output (flattened, f32):
//   [0, 8388608)        z_q_st  [B, D, H, W]
//   [8388608]           commitment_loss
//   [8388609, 8519681)  indices [B, H, W] as f32
//
// Exactness strategy: fp32 pass tracks the TOP-2 candidates per token; both
// are rescored in fp64 (exact for fp32 inputs) and compared with lower-index
// tie-break. This matches the reference argmin except for true gaps below the
// reference's own fp32 rounding (~3e-5), which is the irreducible floor.
// ---------------------------------------------------------------------------

#define BB   32
#define DD   64
#define HH   64
#define WW   64
#define HW   (HH * WW)          // 4096
#define NTOK (BB * HW)          // 131072
#define KK   1024
#define CHUNK 128               // codes staged in smem per pass (32 KB)
#define TPB  256

#define ZQ_ELEMS   ((size_t)BB * DD * HW)   // 8388608
#define LOSS_OFF   (ZQ_ELEMS)               // 8388608
#define IDX_OFF    (ZQ_ELEMS + 1)           // 8388609

__device__ float g_enorm[KK];
__device__ float g_loss_accum;

// Kernel 0: per-code squared norms + zero the loss accumulator (every launch).
__global__ void vq_prep_kernel(const float* __restrict__ embed) {
    int c = blockIdx.x * blockDim.x + threadIdx.x;
    if (c < KK) {
        const float4* row = reinterpret_cast<const float4*>(embed + (size_t)c * DD);
        float s = 0.f;
#pragma unroll
        for (int i = 0; i < DD / 4; i++) {
            float4 v = row[i];
            s = fmaf(v.x, v.x, s);
            s = fmaf(v.y, v.y, s);
            s = fmaf(v.z, v.z, s);
            s = fmaf(v.w, v.w, s);
        }
        g_enorm[c] = s;
    }
    if (blockIdx.x == 0 && threadIdx.x == 0) g_loss_accum = 0.f;
}

// Exact fp64 score of one code against the token vector x (fp32 inputs).
__device__ __forceinline__ double exact_score(const float* __restrict__ e,
                                              const float* __restrict__ x) {
    double nrm = 0.0, dot = 0.0;
#pragma unroll
    for (int d = 0; d < DD; d++) {
        double ev = (double)__ldg(&e[d]);
        nrm = fma(ev, ev, nrm);
        dot = fma((double)x[d], ev, dot);
    }
    return nrm - 2.0 * dot;   // ||x||^2 constant per token: same argmin
}

// Kernel 1: main — one token per thread.
__global__ __launch_bounds__(TPB, 2)
void vq_main_kernel(const float* __restrict__ z_e,
                    const float* __restrict__ embed,
                    float* __restrict__ out) {
    __shared__ float es[CHUNK][DD];   // 32 KB code chunk
    __shared__ float en[CHUNK];       // chunk norms
    __shared__ float red[TPB / 32];   // loss reduction scratch

    const int n  = blockIdx.x * TPB + threadIdx.x;   // token id (grid exact)
    const int b  = n / HW;
    const int hw = n % HW;
    const float* xp = z_e + (size_t)b * DD * HW + hw;

    float x[DD];
#pragma unroll
    for (int d = 0; d < DD; d++) x[d] = xp[(size_t)d * HW];

    float best = FLT_MAX, second = FLT_MAX;
    int   bidx = 0,       sidx   = 1;

    for (int c0 = 0; c0 < KK; c0 += CHUNK) {
        __syncthreads();
        {
            const float4* src = reinterpret_cast<const float4*>(embed + (size_t)c0 * DD);
            float4* dst = reinterpret_cast<float4*>(&es[0][0]);
#pragma unroll
            for (int i = threadIdx.x; i < CHUNK * DD / 4; i += TPB) dst[i] = src[i];
            for (int i = threadIdx.x; i < CHUNK; i += TPB) en[i] = g_enorm[c0 + i];
        }
        __syncthreads();

#pragma unroll 1
        for (int c = 0; c < CHUNK; c += 2) {
            float a0 = 0.f, a1 = 0.f, a2 = 0.f, a3 = 0.f;
            float q0 = 0.f, q1 = 0.f, q2 = 0.f, q3 = 0.f;
#pragma unroll
            for (int d = 0; d < DD; d += 4) {
                a0 = fmaf(x[d + 0], es[c][d + 0], a0);
                a1 = fmaf(x[d + 1], es[c][d + 1], a1);
                a2 = fmaf(x[d + 2], es[c][d + 2], a2);
                a3 = fmaf(x[d + 3], es[c][d + 3], a3);
                q0 = fmaf(x[d + 0], es[c + 1][d + 0], q0);
                q1 = fmaf(x[d + 1], es[c + 1][d + 1], q1);
                q2 = fmaf(x[d + 2], es[c + 1][d + 2], q2);
                q3 = fmaf(x[d + 3], es[c + 1][d + 3], q3);
            }
            float s0 = en[c]     - 2.f * ((a0 + a1) + (a2 + a3));
            float s1 = en[c + 1] - 2.f * ((q0 + q1) + (q2 + q3));

            // top-2 tracking (strict <: first-occurrence order preserved)
            if (s0 < best)        { second = best; sidx = bidx; best = s0; bidx = c0 + c; }
            else if (s0 < second) { second = s0;   sidx = c0 + c; }
            if (s1 < best)        { second = best; sidx = bidx; best = s1; bidx = c0 + c + 1; }
            else if (s1 < second) { second = s1;   sidx = c0 + c + 1; }
        }
    }

    // Exact fp64 rescore of the two candidates; lower index wins ties.
    {
        double sb = exact_score(embed + (size_t)bidx * DD, x);
        double ss = exact_score(embed + (size_t)sidx * DD, x);
        if (ss < sb || (ss == sb && sidx < bidx)) bidx = sidx;
    }

    // Gather winner, write straight-through output, accumulate loss.
    const float* e = embed + (size_t)bidx * DD;
    float lsum = 0.f;
#pragma unroll
    for (int d = 0; d < DD; d++) {
        float ev   = __ldg(&e[d]);
        float xv   = x[d];
        float diff = ev - xv;                       // (z_q - z_e)
        lsum = fmaf(diff, diff, lsum);
        out[(size_t)b * DD * HW + (size_t)d * HW + hw] = xv + diff;  // z_e + (z_q - z_e)
    }
    out[IDX_OFF + (size_t)n] = (float)bidx;

    const int lane = threadIdx.x & 31;
    const int wid  = threadIdx.x >> 5;
#pragma unroll
    for (int o = 16; o > 0; o >>= 1) lsum += __shfl_down_sync(0xFFFFFFFFu, lsum, o);
    if (lane == 0) red[wid] = lsum;
    __syncthreads();
    if (wid == 0) {
        float v = (lane < TPB / 32) ? red[lane] : 0.f;
#pragma unroll
        for (int o = 4; o > 0; o >>= 1) v += __shfl_down_sync(0xFFFFFFFFu, v, o);
        if (lane == 0) atomicAdd(&g_loss_accum, v);
    }
}

// Kernel 2: finalize the scalar loss.
__global__ void vq_finalize_kernel(float* __restrict__ out) {
    if (threadIdx.x == 0 && blockIdx.x == 0) {
        out[LOSS_OFF] = g_loss_accum / (float)((size_t)NTOK * DD);
    }
}

extern "C" void kernel_launch(void* const* d_in, const int* in_sizes, int n_in,
                              void* d_out, int out_size) {
    const float* z_e   = (const float*)d_in[0];
    const float* embed = (const float*)d_in[1];
    float* out = (float*)d_out;

    vq_prep_kernel<<<(KK + TPB - 1) / TPB, TPB>>>(embed);
    vq_main_kernel<<<NTOK / TPB, TPB>>>(z_e, embed, out);
    vq_finalize_kernel<<<1, 32>>>(out);
}

// round 6
// speedup vs baseline: 3.1314x; 3.1314x over previous
#include <cuda_runtime.h>
#include <cuda_bf16.h>
#include <cstdint>
#include <cfloat>

// ---------------------------------------------------------------------------
// VectorQuantize forward: split-bf16 mma.sync tensor-core screen (x = hi+lo,
// e = bf16; score noise sigma ~0.025) + top-3/thread candidate tracking +
// fp64 exact rescore of near-ties (theta = 10 sigma).
//
//   z_e   : [B=32, D=64, H=64, W=64] f32
//   embed : [K=1024, D=64] f32
// Output (f32): [0,8388608) z_q_st | [8388608] loss | [8388609,8519681) idx
// ---------------------------------------------------------------------------

#define DD     64
#define HW     4096
#define NTOK   131072
#define KK     1024
#define TPB    256
#define MT_CTA 256          // tokens per CTA (8 warps x 32)

#define ZQ_ELEMS 8388608UL
#define LOSS_OFF 8388608UL
#define IDX_OFF  8388609UL

#define ESTRIDE 144         // smem codebook row stride (bytes): conflict-free B LDS
#define SM_ES   0                            // codebook bf16, 1024 x 144B = 147456
#define SM_XS   (KK * ESTRIDE)               // X fp32 [64][256] d-major, 65536
#define SM_EN   (SM_XS + DD * MT_CTA * 4)    // ||e||^2 fp32 [1024], 4096
#define SM_SIDX (SM_EN + KK * 4)             // winner per token, 1024
#define SM_RED  (SM_SIDX + MT_CTA * 4)       // loss reduction, 64
#define SMEM_TOTAL (SM_RED + 64)             // 218176 B

#define THETA 0.25f         // rescore trigger: ~10 sigma of split-bf16 noise

__device__ float  g_enorm[KK];
__device__ double g_enormd[KK];
__device__ float  g_loss_accum;
__device__ __align__(16) __nv_bfloat16 g_ebf[KK * DD];

// ---------------------------------------------------------------------------
// Prep: fp32+fp64 norms, bf16 codebook, zero loss. One thread per code.
__global__ void vq_prep_kernel(const float* __restrict__ embed) {
    int c = blockIdx.x * blockDim.x + threadIdx.x;
    if (c < KK) {
        const float4* row = (const float4*)(embed + (size_t)c * DD);
        float s = 0.f; double sd = 0.0;
        uint32_t pk[32];
#pragma unroll
        for (int i = 0; i < 16; i++) {
            float4 v = row[i];
            s = fmaf(v.x, v.x, s); s = fmaf(v.y, v.y, s);
            s = fmaf(v.z, v.z, s); s = fmaf(v.w, v.w, s);
            sd = fma((double)v.x, (double)v.x, sd);
            sd = fma((double)v.y, (double)v.y, sd);
            sd = fma((double)v.z, (double)v.z, sd);
            sd = fma((double)v.w, (double)v.w, sd);
            __nv_bfloat162 p0 = __floats2bfloat162_rn(v.x, v.y);
            __nv_bfloat162 p1 = __floats2bfloat162_rn(v.z, v.w);
            pk[2 * i]     = *(uint32_t*)&p0;
            pk[2 * i + 1] = *(uint32_t*)&p1;
        }
        g_enorm[c] = s; g_enormd[c] = sd;
        uint4* dst = (uint4*)(g_ebf + (size_t)c * DD);
#pragma unroll
        for (int i = 0; i < 8; i++)
            dst[i] = make_uint4(pk[4 * i], pk[4 * i + 1], pk[4 * i + 2], pk[4 * i + 3]);
    }
    if (blockIdx.x == 0 && threadIdx.x == 0) g_loss_accum = 0.f;
}

// sortable-key top-3 update: key = order(f32 bits), low 10 bits = code idx
// (ties auto-break to lower index; quantization << THETA so covered by rescore)
__device__ __forceinline__ void upd3(uint32_t& k1, uint32_t& k2, uint32_t& k3,
                                     float sc, int code) {
    uint32_t u = __float_as_uint(sc);
    u ^= (uint32_t)((int)u >> 31) | 0x80000000u;
    u = (u & 0xFFFFFC00u) | (uint32_t)code;
    uint32_t t1 = min(k1, u);
    uint32_t h1 = max(k1, u);
    uint32_t t2 = min(k2, h1);
    uint32_t h2 = max(k2, h1);
    k3 = min(k3, h2);
    k2 = t2;
    k1 = t1;
}
__device__ __forceinline__ float key2f(uint32_t k) {
    uint32_t u = (k & 0x80000000u) ? (k ^ 0x80000000u) : ~k;
    return __uint_as_float(u);
}

// ---------------------------------------------------------------------------
__global__ __launch_bounds__(TPB, 1)
void vq_main_kernel(const float* __restrict__ z_e,
                    const float* __restrict__ embed,
                    float* __restrict__ out) {
    extern __shared__ __align__(16) char smem[];
    float* Xs   = (float*)(smem + SM_XS);
    float* en_s = (float*)(smem + SM_EN);
    int*   Sidx = (int*)(smem + SM_SIDX);
    float* Red  = (float*)(smem + SM_RED);

    const int tid = threadIdx.x, wid = tid >> 5, lane = tid & 31;
    const int g = lane >> 2, tig = lane & 3;
    const int base = blockIdx.x * MT_CTA;
    const int b = base / HW, hw0 = base % HW;
    const float* zbase = z_e + (size_t)b * DD * HW + hw0;

    // Stage X (coalesced), codebook bf16 (128B rows -> 144B-stride), norms.
    for (int i = tid; i < DD * MT_CTA; i += TPB)
        Xs[i] = zbase[(size_t)(i >> 8) * HW + (i & 255)];
    {
        const uint4* src = (const uint4*)g_ebf;
        for (int i = tid; i < KK * 8; i += TPB)
            *(uint4*)(smem + SM_ES + (i >> 3) * ESTRIDE + (i & 7) * 16) = src[i];
    }
    for (int i = tid; i < KK; i += TPB) en_s[i] = g_enorm[i];
    __syncthreads();

    // Build split A fragments once: warp owns tokens [wid*32, wid*32+32).
    // x = x_hi(bf16) + x_lo(bf16): screen error dominated by e rounding only.
    const int trow0 = wid * 32;
    uint32_t Ahi[4][2][4], Alo[4][2][4];
#pragma unroll
    for (int kt = 0; kt < 4; kt++)
#pragma unroll
        for (int mt = 0; mt < 2; mt++) {
            const int ta = trow0 + mt * 16 + g, tb = ta + 8;
            const int c0 = kt * 16 + tig * 2;
#pragma unroll
            for (int h = 0; h < 2; h++) {
                const int cc = c0 + h * 8;
                float xa0 = Xs[cc * MT_CTA + ta], xa1 = Xs[(cc + 1) * MT_CTA + ta];
                float xb0 = Xs[cc * MT_CTA + tb], xb1 = Xs[(cc + 1) * MT_CTA + tb];
                __nv_bfloat16 ha0 = __float2bfloat16_rn(xa0);
                __nv_bfloat16 ha1 = __float2bfloat16_rn(xa1);
                __nv_bfloat16 hb0 = __float2bfloat16_rn(xb0);
                __nv_bfloat16 hb1 = __float2bfloat16_rn(xb1);
                __nv_bfloat16 la0 = __float2bfloat16_rn(xa0 - __bfloat162float(ha0));
                __nv_bfloat16 la1 = __float2bfloat16_rn(xa1 - __bfloat162float(ha1));
                __nv_bfloat16 lb0 = __float2bfloat16_rn(xb0 - __bfloat162float(hb0));
                __nv_bfloat16 lb1 = __float2bfloat16_rn(xb1 - __bfloat162float(hb1));
                __nv_bfloat162 pha = __halves2bfloat162(ha0, ha1);
                __nv_bfloat162 phb = __halves2bfloat162(hb0, hb1);
                __nv_bfloat162 pla = __halves2bfloat162(la0, la1);
                __nv_bfloat162 plb = __halves2bfloat162(lb0, lb1);
                Ahi[kt][mt][2 * h]     = *(uint32_t*)&pha;
                Ahi[kt][mt][2 * h + 1] = *(uint32_t*)&phb;
                Alo[kt][mt][2 * h]     = *(uint32_t*)&pla;
                Alo[kt][mt][2 * h + 1] = *(uint32_t*)&plb;
            }
        }

    // Screen mainloop: 128 n-tiles of 8 codes, top-3 per thread per row.
    uint32_t k1[4], k2[4], k3[4];
#pragma unroll
    for (int r = 0; r < 4; r++) { k1[r] = k2[r] = k3[r] = 0xFFFFFFFFu; }

#pragma unroll 2
    for (int nt = 0; nt < KK / 8; nt++) {
        const int cb = nt * 8;
        const char* brow = smem + SM_ES + (cb + g) * ESTRIDE + tig * 4;
        uint32_t B0[4], B1[4];
#pragma unroll
        for (int kt = 0; kt < 4; kt++) {
            B0[kt] = *(const uint32_t*)(brow + kt * 32);
            B1[kt] = *(const uint32_t*)(brow + kt * 32 + 16);
        }
        const float2 en2 = *(const float2*)(en_s + cb + tig * 2);
        const int n0 = cb + tig * 2;
#pragma unroll
        for (int mt = 0; mt < 2; mt++) {
            float d0 = 0.f, d1 = 0.f, d2 = 0.f, d3 = 0.f;
#pragma unroll
            for (int kt = 0; kt < 4; kt++) {
                asm volatile(
                    "mma.sync.aligned.m16n8k16.row.col.f32.bf16.bf16.f32 "
                    "{%0,%1,%2,%3}, {%4,%5,%6,%7}, {%8,%9}, {%0,%1,%2,%3};"
                    : "+f"(d0), "+f"(d1), "+f"(d2), "+f"(d3)
                    : "r"(Ahi[kt][mt][0]), "r"(Ahi[kt][mt][1]),
                      "r"(Ahi[kt][mt][2]), "r"(Ahi[kt][mt][3]),
                      "r"(B0[kt]), "r"(B1[kt]));
                asm volatile(
                    "mma.sync.aligned.m16n8k16.row.col.f32.bf16.bf16.f32 "
                    "{%0,%1,%2,%3}, {%4,%5,%6,%7}, {%8,%9}, {%0,%1,%2,%3};"
                    : "+f"(d0), "+f"(d1), "+f"(d2), "+f"(d3)
                    : "r"(Alo[kt][mt][0]), "r"(Alo[kt][mt][1]),
                      "r"(Alo[kt][mt][2]), "r"(Alo[kt][mt][3]),
                      "r"(B0[kt]), "r"(B1[kt]));
            }
            upd3(k1[mt * 2],     k2[mt * 2],     k3[mt * 2],     fmaf(d0, -2.f, en2.x), n0);
            upd3(k1[mt * 2],     k2[mt * 2],     k3[mt * 2],     fmaf(d1, -2.f, en2.y), n0 + 1);
            upd3(k1[mt * 2 + 1], k2[mt * 2 + 1], k3[mt * 2 + 1], fmaf(d2, -2.f, en2.x), n0);
            upd3(k1[mt * 2 + 1], k2[mt * 2 + 1], k3[mt * 2 + 1], fmaf(d3, -2.f, en2.y), n0 + 1);
        }
    }

    // Resolve winners: quad-merge top-2 for the gap test; on a near-tie,
    // fp64-rescore all 12 quad candidates (3 per thread) and quad-reduce.
    const uint32_t qmask = 0xFu << (lane & 28);
#pragma unroll
    for (int r = 0; r < 4; r++) {
        uint32_t a1 = k1[r], a2 = k2[r];
#pragma unroll
        for (int off = 1; off < 4; off <<= 1) {
            uint32_t b1 = __shfl_xor_sync(0xFFFFFFFFu, a1, off);
            uint32_t b2 = __shfl_xor_sync(0xFFFFFFFFu, a2, off);
            uint32_t m1 = min(a1, b1);
            uint32_t m2 = min(max(a1, b1), min(a2, b2));
            a1 = m1; a2 = m2;
        }
        const int lt = trow0 + (r >> 1) * 16 + g + ((r & 1) ? 8 : 0);
        int winner;
        const bool need = (key2f(a2) - key2f(a1)) < THETA;   // quad-uniform
        if (need) {
            double bs = 1e300; int bi = 1 << 20;
            const uint32_t kr[3] = { k1[r], k2[r], k3[r] };
#pragma unroll
            for (int cc = 0; cc < 3; cc++) {
                const int idx = (int)(kr[cc] & 1023u);
                const float4* er = (const float4*)(embed + (size_t)idx * DD);
                double dot = 0.0;
#pragma unroll
                for (int i = 0; i < 16; i++) {
                    float4 v = __ldg(er + i);
                    dot = fma((double)v.x, (double)Xs[(4 * i + 0) * MT_CTA + lt], dot);
                    dot = fma((double)v.y, (double)Xs[(4 * i + 1) * MT_CTA + lt], dot);
                    dot = fma((double)v.z, (double)Xs[(4 * i + 2) * MT_CTA + lt], dot);
                    dot = fma((double)v.w, (double)Xs[(4 * i + 3) * MT_CTA + lt], dot);
                }
                double sc = g_enormd[idx] - 2.0 * dot;
                if (sc < bs || (sc == bs && idx < bi)) { bs = sc; bi = idx; }
            }
#pragma unroll
            for (int off = 1; off < 4; off <<= 1) {
                double os = __shfl_xor_sync(qmask, bs, off);
                int    oi = __shfl_xor_sync(qmask, bi, off);
                if (os < bs || (os == bs && oi < bi)) { bs = os; bi = oi; }
            }
            winner = bi;
        } else {
            winner = (int)(a1 & 1023u);
        }
        if (tig == 0) {
            Sidx[lt] = winner;
            out[IDX_OFF + (size_t)(base + lt)] = (float)winner;
        }
    }
    __syncthreads();

    // Epilogue: gather winner rows (reuse codebook smem), coalesced ST output.
    float* Eg = (float*)(smem + SM_ES);          // [256][65] floats
    {
        const int lt = tid;
        const int bi = Sidx[lt];
        const float4* er = (const float4*)(embed + (size_t)bi * DD);
#pragma unroll
        for (int i = 0; i < 16; i++) {
            float4 v = __ldg(er + i);
            Eg[lt * 65 + 4 * i + 0] = v.x; Eg[lt * 65 + 4 * i + 1] = v.y;
            Eg[lt * 65 + 4 * i + 2] = v.z; Eg[lt * 65 + 4 * i + 3] = v.w;
        }
    }
    __syncthreads();

    float lsum = 0.f;
    for (int i = tid; i < DD * MT_CTA; i += TPB) {
        const int d = i >> 8, t = i & 255;
        float xv = Xs[i];
        float diff = Eg[t * 65 + d] - xv;
        lsum = fmaf(diff, diff, lsum);
        out[(size_t)b * DD * HW + (size_t)d * HW + hw0 + t] = xv + diff;
    }
#pragma unroll
    for (int o = 16; o > 0; o >>= 1) lsum += __shfl_down_sync(0xFFFFFFFFu, lsum, o);
    if (lane == 0) Red[wid] = lsum;
    __syncthreads();
    if (wid == 0) {
        float v = (lane < TPB / 32) ? Red[lane] : 0.f;
#pragma unroll
        for (int o = 4; o > 0; o >>= 1) v += __shfl_down_sync(0xFFFFFFFFu, v, o);
        if (lane == 0) atomicAdd(&g_loss_accum, v);
    }
}

__global__ void vq_finalize_kernel(float* __restrict__ out) {
    if (threadIdx.x == 0 && blockIdx.x == 0)
        out[LOSS_OFF] = g_loss_accum / (float)((size_t)NTOK * DD);
}

extern "C" void kernel_launch(void* const* d_in, const int* in_sizes, int n_in,
                              void* d_out, int out_size) {
    const float* z_e   = (const float*)d_in[0];
    const float* embed = (const float*)d_in[1];
    float* out = (float*)d_out;

    cudaFuncSetAttribute(vq_main_kernel,
                         cudaFuncAttributeMaxDynamicSharedMemorySize, SMEM_TOTAL);
    vq_prep_kernel<<<4, 256>>>(embed);
    vq_main_kernel<<<NTOK / MT_CTA, TPB, SMEM_TOTAL>>>(z_e, embed, out);
    vq_finalize_kernel<<<1, 32>>>(out);
}

// round 7
// speedup vs baseline: 3.6783x; 1.1747x over previous
#include <cuda_runtime.h>
#include <cuda_fp16.h>
#include <cstdint>
#include <cfloat>

// ---------------------------------------------------------------------------
// VectorQuantize forward: fp16 mma.sync tensor-core screen (sigma ~0.009) +
// top-4/thread candidates + pruned fp64 exact rescore of near-ties.
// Legacy mma path only: harness compiles at plain sm_100 (no tcgen05).
//
//   z_e   : [B=32, D=64, H=64, W=64] f32
//   embed : [K=1024, D=64] f32
// Output (f32): [0,8388608) z_q_st | [8388608] loss | [8388609,8519681) idx
// ---------------------------------------------------------------------------

#define DD     64
#define HW     4096
#define NTOK   131072
#define KK     1024
#define TPB    256
#define MT_CTA 256          // tokens per CTA (8 warps x 32)
#define NCTA   (NTOK / MT_CTA)   // 512

#define ZQ_ELEMS 8388608UL
#define LOSS_OFF 8388608UL
#define IDX_OFF  8388609UL

#define ESTRIDE 144         // smem codebook row stride (bytes): conflict-free B LDS
#define SM_ES   0                            // codebook fp16, 1024 x 144B = 147456
#define SM_XS   (KK * ESTRIDE)               // X fp32 [64][256] d-major, 65536
#define SM_EN   (SM_XS + DD * MT_CTA * 4)    // ||e||^2 fp32 [1024], 4096
#define SM_SIDX (SM_EN + KK * 4)             // winner per token, 1024
#define SM_RED  (SM_SIDX + MT_CTA * 4)       // loss reduction, 64
#define SMEM_TOTAL (SM_RED + 64)             // 218176 B

#define THETA 0.12f         // rescore trigger/prune window (~9 sigma fp16 screen)

__device__ float g_part[NCTA];   // per-CTA loss partials (written every launch)

// sortable-key top-4 update: key = order(f32 bits), low 10 bits = code idx
__device__ __forceinline__ void upd4(uint32_t& k1, uint32_t& k2, uint32_t& k3,
                                     uint32_t& k4, float sc, int code) {
    uint32_t u = __float_as_uint(sc);
    u ^= (uint32_t)((int)u >> 31) | 0x80000000u;
    u = (u & 0xFFFFFC00u) | (uint32_t)code;
    uint32_t t1 = min(k1, u);
    uint32_t h1 = max(k1, u);
    uint32_t t2 = min(k2, h1);
    uint32_t h2 = max(k2, h1);
    uint32_t t3 = min(k3, h2);
    uint32_t h3 = max(k3, h2);
    k4 = min(k4, h3);
    k3 = t3; k2 = t2; k1 = t1;
}
__device__ __forceinline__ float key2f(uint32_t k) {
    uint32_t u = (k & 0x80000000u) ? (k ^ 0x80000000u) : ~k;
    return __uint_as_float(u);
}

// ---------------------------------------------------------------------------
__global__ __launch_bounds__(TPB, 1)
void vq_main_kernel(const float* __restrict__ z_e,
                    const float* __restrict__ embed,
                    float* __restrict__ out) {
    extern __shared__ __align__(16) char smem[];
    float* Xs   = (float*)(smem + SM_XS);
    float* en_s = (float*)(smem + SM_EN);
    int*   Sidx = (int*)(smem + SM_SIDX);
    float* Red  = (float*)(smem + SM_RED);

    const int tid = threadIdx.x, wid = tid >> 5, lane = tid & 31;
    const int g = lane >> 2, tig = lane & 3;
    const int base = blockIdx.x * MT_CTA;
    const int b = base / HW, hw0 = base % HW;
    const float* zbase = z_e + (size_t)b * DD * HW + hw0;

    // Stage X (coalesced) and codebook fp32 -> fp16 smem + fp32 norms.
    for (int i = tid; i < DD * MT_CTA; i += TPB)
        Xs[i] = zbase[(size_t)(i >> 8) * HW + (i & 255)];
    for (int r = tid; r < KK; r += TPB) {
        const float4* row = (const float4*)(embed + (size_t)r * DD);
        char* dst = smem + SM_ES + r * ESTRIDE;
        float s = 0.f;
#pragma unroll
        for (int i = 0; i < 16; i++) {
            float4 v = __ldg(row + i);
            s = fmaf(v.x, v.x, s); s = fmaf(v.y, v.y, s);
            s = fmaf(v.z, v.z, s); s = fmaf(v.w, v.w, s);
            __half2 h0 = __floats2half2_rn(v.x, v.y);
            __half2 h1 = __floats2half2_rn(v.z, v.w);
            *(uint2*)(dst + i * 8) = make_uint2(*(uint32_t*)&h0, *(uint32_t*)&h1);
        }
        en_s[r] = s;
    }
    __syncthreads();

    // Build fp16 A fragments once: warp owns tokens [wid*32, wid*32+32).
    const int trow0 = wid * 32;
    uint32_t A[4][2][4];
#pragma unroll
    for (int kt = 0; kt < 4; kt++)
#pragma unroll
        for (int mt = 0; mt < 2; mt++) {
            const int ta = trow0 + mt * 16 + g, tb = ta + 8;
            const int c0 = kt * 16 + tig * 2;
#pragma unroll
            for (int h = 0; h < 2; h++) {
                const int cc = c0 + h * 8;
                __half2 pa = __floats2half2_rn(Xs[cc * MT_CTA + ta],
                                               Xs[(cc + 1) * MT_CTA + ta]);
                __half2 pb = __floats2half2_rn(Xs[cc * MT_CTA + tb],
                                               Xs[(cc + 1) * MT_CTA + tb]);
                A[kt][mt][2 * h]     = *(uint32_t*)&pa;
                A[kt][mt][2 * h + 1] = *(uint32_t*)&pb;
            }
        }

    // Screen mainloop: 128 n-tiles of 8 codes, top-4 per thread per row.
    uint32_t k1[4], k2[4], k3[4], k4[4];
#pragma unroll
    for (int r = 0; r < 4; r++) { k1[r] = k2[r] = k3[r] = k4[r] = 0xFFFFFFFFu; }

#pragma unroll 2
    for (int nt = 0; nt < KK / 8; nt++) {
        const int cb = nt * 8;
        const char* brow = smem + SM_ES + (cb + g) * ESTRIDE + tig * 4;
        uint32_t B0[4], B1[4];
#pragma unroll
        for (int kt = 0; kt < 4; kt++) {
            B0[kt] = *(const uint32_t*)(brow + kt * 32);
            B1[kt] = *(const uint32_t*)(brow + kt * 32 + 16);
        }
        const float2 en2 = *(const float2*)(en_s + cb + tig * 2);
        const int n0 = cb + tig * 2;
#pragma unroll
        for (int mt = 0; mt < 2; mt++) {
            float d0 = 0.f, d1 = 0.f, d2 = 0.f, d3 = 0.f;
#pragma unroll
            for (int kt = 0; kt < 4; kt++) {
                asm volatile(
                    "mma.sync.aligned.m16n8k16.row.col.f32.f16.f16.f32 "
                    "{%0,%1,%2,%3}, {%4,%5,%6,%7}, {%8,%9}, {%0,%1,%2,%3};"
                    : "+f"(d0), "+f"(d1), "+f"(d2), "+f"(d3)
                    : "r"(A[kt][mt][0]), "r"(A[kt][mt][1]),
                      "r"(A[kt][mt][2]), "r"(A[kt][mt][3]),
                      "r"(B0[kt]), "r"(B1[kt]));
            }
            upd4(k1[mt*2],   k2[mt*2],   k3[mt*2],   k4[mt*2],   fmaf(d0, -2.f, en2.x), n0);
            upd4(k1[mt*2],   k2[mt*2],   k3[mt*2],   k4[mt*2],   fmaf(d1, -2.f, en2.y), n0 + 1);
            upd4(k1[mt*2+1], k2[mt*2+1], k3[mt*2+1], k4[mt*2+1], fmaf(d2, -2.f, en2.x), n0);
            upd4(k1[mt*2+1], k2[mt*2+1], k3[mt*2+1], k4[mt*2+1], fmaf(d3, -2.f, en2.y), n0 + 1);
        }
    }

    // Resolve winners: quad-merge top-2 for the gap test; on a near-tie each
    // thread fp64-rescores only its candidates within THETA of the quad best.
    const uint32_t qmask = 0xFu << (lane & 28);
#pragma unroll
    for (int r = 0; r < 4; r++) {
        uint32_t a1 = k1[r], a2 = k2[r];
#pragma unroll
        for (int off = 1; off < 4; off <<= 1) {
            uint32_t b1 = __shfl_xor_sync(0xFFFFFFFFu, a1, off);
            uint32_t b2 = __shfl_xor_sync(0xFFFFFFFFu, a2, off);
            uint32_t m1 = min(a1, b1);
            uint32_t m2 = min(max(a1, b1), min(a2, b2));
            a1 = m1; a2 = m2;
        }
        const int lt = trow0 + (r >> 1) * 16 + g + ((r & 1) ? 8 : 0);
        int winner;
        const float a1f = key2f(a1);
        const bool need = (key2f(a2) - a1f) < THETA;   // quad-uniform
        if (need) {
            const float cut = a1f + THETA;
            double bs = 1e300; int bi = 1 << 20;
            const uint32_t kr[4] = { k1[r], k2[r], k3[r], k4[r] };
#pragma unroll
            for (int cc = 0; cc < 4; cc++) {
                if (key2f(kr[cc]) <= cut) {
                    const int idx = (int)(kr[cc] & 1023u);
                    const float4* er = (const float4*)(embed + (size_t)idx * DD);
                    double nrm = 0.0, dot = 0.0;
#pragma unroll
                    for (int i = 0; i < 16; i++) {
                        float4 v = __ldg(er + i);
                        double e0 = v.x, e1 = v.y, e2 = v.z, e3 = v.w;
                        nrm = fma(e0, e0, nrm); nrm = fma(e1, e1, nrm);
                        nrm = fma(e2, e2, nrm); nrm = fma(e3, e3, nrm);
                        dot = fma(e0, (double)Xs[(4*i+0) * MT_CTA + lt], dot);
                        dot = fma(e1, (double)Xs[(4*i+1) * MT_CTA + lt], dot);
                        dot = fma(e2, (double)Xs[(4*i+2) * MT_CTA + lt], dot);
                        dot = fma(e3, (double)Xs[(4*i+3) * MT_CTA + lt], dot);
                    }
                    double sc = nrm - 2.0 * dot;
                    if (sc < bs || (sc == bs && idx < bi)) { bs = sc; bi = idx; }
                }
            }
#pragma unroll
            for (int off = 1; off < 4; off <<= 1) {
                double os = __shfl_xor_sync(qmask, bs, off);
                int    oi = __shfl_xor_sync(qmask, bi, off);
                if (os < bs || (os == bs && oi < bi)) { bs = os; bi = oi; }
            }
            winner = bi;
        } else {
            winner = (int)(a1 & 1023u);
        }
        if (tig == 0) {
            Sidx[lt] = winner;
            out[IDX_OFF + (size_t)(base + lt)] = (float)winner;
        }
    }
    __syncthreads();

    // Epilogue: gather winner rows (reuse codebook smem), coalesced ST output.
    float* Eg = (float*)(smem + SM_ES);          // [256][65] floats
    {
        const int lt = tid;
        const int bi = Sidx[lt];
        const float4* er = (const float4*)(embed + (size_t)bi * DD);
#pragma unroll
        for (int i = 0; i < 16; i++) {
            float4 v = __ldg(er + i);
            Eg[lt * 65 + 4 * i + 0] = v.x; Eg[lt * 65 + 4 * i + 1] = v.y;
            Eg[lt * 65 + 4 * i + 2] = v.z; Eg[lt * 65 + 4 * i + 3] = v.w;
        }
    }
    __syncthreads();

    float lsum = 0.f;
    for (int i = tid; i < DD * MT_CTA; i += TPB) {
        const int d = i >> 8, t = i & 255;
        float xv = Xs[i];
        float diff = Eg[t * 65 + d] - xv;
        lsum = fmaf(diff, diff, lsum);
        out[(size_t)b * DD * HW + (size_t)d * HW + hw0 + t] = xv + diff;
    }
#pragma unroll
    for (int o = 16; o > 0; o >>= 1) lsum += __shfl_down_sync(0xFFFFFFFFu, lsum, o);
    if (lane == 0) Red[wid] = lsum;
    __syncthreads();
    if (wid == 0) {
        float v = (lane < TPB / 32) ? Red[lane] : 0.f;
#pragma unroll
        for (int o = 4; o > 0; o >>= 1) v += __shfl_down_sync(0xFFFFFFFFu, v, o);
        if (lane == 0) g_part[blockIdx.x] = v;    // no atomics: fixed slot
    }
}

// Sum the 512 per-CTA partials (deterministic order) and write the loss.
__global__ void vq_finalize_kernel(float* __restrict__ out) {
    __shared__ float red[8];
    const int tid = threadIdx.x, lane = tid & 31, wid = tid >> 5;
    float v = g_part[tid] + g_part[tid + 256];
#pragma unroll
    for (int o = 16; o > 0; o >>= 1) v += __shfl_down_sync(0xFFFFFFFFu, v, o);
    if (lane == 0) red[wid] = v;
    __syncthreads();
    if (wid == 0) {
        float s = (lane < 8) ? red[lane] : 0.f;
#pragma unroll
        for (int o = 4; o > 0; o >>= 1) s += __shfl_down_sync(0xFFFFFFFFu, s, o);
        if (lane == 0) out[LOSS_OFF] = s / (float)((size_t)NTOK * DD);
    }
}

extern "C" void kernel_launch(void* const* d_in, const int* in_sizes, int n_in,
                              void* d_out, int out_size) {
    const float* z_e   = (const float*)d_in[0];
    const float* embed = (const float*)d_in[1];
    float* out = (float*)d_out;

    cudaFuncSetAttribute(vq_main_kernel,
                         cudaFuncAttributeMaxDynamicSharedMemorySize, SMEM_TOTAL);
    vq_main_kernel<<<NCTA, TPB, SMEM_TOTAL>>>(z_e, embed, out);
    vq_finalize_kernel<<<1, 256>>>(out);
}

// round 8
// speedup vs baseline: 4.0909x; 1.1122x over previous
#include <cuda_runtime.h>
#include <cuda_fp16.h>
#include <cstdint>
#include <cfloat>

// ---------------------------------------------------------------------------
// VectorQuantize forward: fp16 mma.sync tensor-core screen + ALU-lean
// positive-key top-3 tracking + pruned fp64 exact rescore of near-ties.
//
//   z_e   : [B=32, D=64, H=64, W=64] f32
//   embed : [K=1024, D=64] f32
// Output (f32): [0,8388608) z_q_st | [8388608] loss | [8388609,8519681) idx
//
// Keys: score+1024 is always a positive float -> uint bits are order-
// preserving; low 10 bits replaced by code index (quantum 0.125, covered by
// THETA). Per score: 1 FFMA + 1 LOP3 + 5 IMNMX.
// ---------------------------------------------------------------------------

#define DD     64
#define HW     4096
#define NTOK   131072
#define KK     1024
#define TPB    256
#define MT_CTA 256          // tokens per CTA (8 warps x 32)
#define NCTA   (NTOK / MT_CTA)   // 512

#define ZQ_ELEMS 8388608UL
#define LOSS_OFF 8388608UL
#define IDX_OFF  8388609UL

#define ESTRIDE 144         // smem codebook row stride (bytes): conflict-free B LDS
#define SM_ES   0                            // codebook fp16, 1024 x 144B = 147456
#define SM_XS   (KK * ESTRIDE)               // X fp32 [64][256] d-major, 65536
#define SM_EN   (SM_XS + DD * MT_CTA * 4)    // ||e||^2+C fp32 [1024], 4096
#define SM_SIDX (SM_EN + KK * 4)             // winner per token, 1024
#define SM_RED  (SM_SIDX + MT_CTA * 4)       // loss reduction, 64
#define SMEM_TOTAL (SM_RED + 64)             // 218176 B

#define CPOS  1024.0f       // positivity offset folded into staged norms
#define THETA 0.35f         // rescore trigger: key quantum 0.125 + screen noise

__device__ float g_part[NCTA];   // per-CTA loss partials (written every launch)

// top-3 update on positive-float keys with embedded index (lower idx wins ties)
__device__ __forceinline__ void upd3(uint32_t& k1, uint32_t& k2, uint32_t& k3,
                                     float sc, int code) {
    uint32_t u = (__float_as_uint(sc) & 0xFFFFFC00u) | (uint32_t)code;  // 1 LOP3
    uint32_t t1 = min(k1, u);
    uint32_t h1 = max(k1, u);
    uint32_t t2 = min(k2, h1);
    uint32_t h2 = max(k2, h1);
    k3 = min(k3, h2);
    k2 = t2; k1 = t1;
}
__device__ __forceinline__ float key2f(uint32_t k) {
    return __uint_as_float(k & 0xFFFFFC00u);
}

// ---------------------------------------------------------------------------
__global__ __launch_bounds__(TPB, 1)
void vq_main_kernel(const float* __restrict__ z_e,
                    const float* __restrict__ embed,
                    float* __restrict__ out) {
    extern __shared__ __align__(16) char smem[];
    float* Xs   = (float*)(smem + SM_XS);
    float* en_s = (float*)(smem + SM_EN);
    int*   Sidx = (int*)(smem + SM_SIDX);
    float* Red  = (float*)(smem + SM_RED);

    const int tid = threadIdx.x, wid = tid >> 5, lane = tid & 31;
    const int g = lane >> 2, tig = lane & 3;
    const int base = blockIdx.x * MT_CTA;
    const int b = base / HW, hw0 = base % HW;
    const float* zbase = z_e + (size_t)b * DD * HW + hw0;

    // Stage X (coalesced) and codebook fp32 -> fp16 smem + (norm + C).
    for (int i = tid; i < DD * MT_CTA; i += TPB)
        Xs[i] = zbase[(size_t)(i >> 8) * HW + (i & 255)];
    for (int r = tid; r < KK; r += TPB) {
        const float4* row = (const float4*)(embed + (size_t)r * DD);
        char* dst = smem + SM_ES + r * ESTRIDE;
        float s = CPOS;
#pragma unroll
        for (int i = 0; i < 16; i++) {
            float4 v = __ldg(row + i);
            s = fmaf(v.x, v.x, s); s = fmaf(v.y, v.y, s);
            s = fmaf(v.z, v.z, s); s = fmaf(v.w, v.w, s);
            __half2 h0 = __floats2half2_rn(v.x, v.y);
            __half2 h1 = __floats2half2_rn(v.z, v.w);
            *(uint2*)(dst + i * 8) = make_uint2(*(uint32_t*)&h0, *(uint32_t*)&h1);
        }
        en_s[r] = s;
    }
    __syncthreads();

    // Build fp16 A fragments once: warp owns tokens [wid*32, wid*32+32).
    const int trow0 = wid * 32;
    uint32_t A[4][2][4];
#pragma unroll
    for (int kt = 0; kt < 4; kt++)
#pragma unroll
        for (int mt = 0; mt < 2; mt++) {
            const int ta = trow0 + mt * 16 + g, tb = ta + 8;
            const int c0 = kt * 16 + tig * 2;
#pragma unroll
            for (int h = 0; h < 2; h++) {
                const int cc = c0 + h * 8;
                __half2 pa = __floats2half2_rn(Xs[cc * MT_CTA + ta],
                                               Xs[(cc + 1) * MT_CTA + ta]);
                __half2 pb = __floats2half2_rn(Xs[cc * MT_CTA + tb],
                                               Xs[(cc + 1) * MT_CTA + tb]);
                A[kt][mt][2 * h]     = *(uint32_t*)&pa;
                A[kt][mt][2 * h + 1] = *(uint32_t*)&pb;
            }
        }

    // Screen mainloop: 128 n-tiles of 8 codes, top-3 per thread per row.
    uint32_t k1[4], k2[4], k3[4];
#pragma unroll
    for (int r = 0; r < 4; r++) { k1[r] = k2[r] = k3[r] = 0x7FFFFFFFu; }

#pragma unroll 4
    for (int nt = 0; nt < KK / 8; nt++) {
        const int cb = nt * 8;
        const char* brow = smem + SM_ES + (cb + g) * ESTRIDE + tig * 4;
        uint32_t B0[4], B1[4];
#pragma unroll
        for (int kt = 0; kt < 4; kt++) {
            B0[kt] = *(const uint32_t*)(brow + kt * 32);
            B1[kt] = *(const uint32_t*)(brow + kt * 32 + 16);
        }
        const float2 en2 = *(const float2*)(en_s + cb + tig * 2);
        const int n0 = cb + tig * 2;
#pragma unroll
        for (int mt = 0; mt < 2; mt++) {
            float d0 = 0.f, d1 = 0.f, d2 = 0.f, d3 = 0.f;
#pragma unroll
            for (int kt = 0; kt < 4; kt++) {
                asm volatile(
                    "mma.sync.aligned.m16n8k16.row.col.f32.f16.f16.f32 "
                    "{%0,%1,%2,%3}, {%4,%5,%6,%7}, {%8,%9}, {%0,%1,%2,%3};"
                    : "+f"(d0), "+f"(d1), "+f"(d2), "+f"(d3)
                    : "r"(A[kt][mt][0]), "r"(A[kt][mt][1]),
                      "r"(A[kt][mt][2]), "r"(A[kt][mt][3]),
                      "r"(B0[kt]), "r"(B1[kt]));
            }
            upd3(k1[mt*2],   k2[mt*2],   k3[mt*2],   fmaf(d0, -2.f, en2.x), n0);
            upd3(k1[mt*2],   k2[mt*2],   k3[mt*2],   fmaf(d1, -2.f, en2.y), n0 + 1);
            upd3(k1[mt*2+1], k2[mt*2+1], k3[mt*2+1], fmaf(d2, -2.f, en2.x), n0);
            upd3(k1[mt*2+1], k2[mt*2+1], k3[mt*2+1], fmaf(d3, -2.f, en2.y), n0 + 1);
        }
    }

    // Resolve winners: quad-merge top-2 for the gap test; on a near-tie each
    // thread fp64-rescores only its candidates within THETA of the quad best.
    const uint32_t qmask = 0xFu << (lane & 28);
#pragma unroll
    for (int r = 0; r < 4; r++) {
        uint32_t a1 = k1[r], a2 = k2[r];
#pragma unroll
        for (int off = 1; off < 4; off <<= 1) {
            uint32_t b1 = __shfl_xor_sync(0xFFFFFFFFu, a1, off);
            uint32_t b2 = __shfl_xor_sync(0xFFFFFFFFu, a2, off);
            uint32_t m1 = min(a1, b1);
            uint32_t m2 = min(max(a1, b1), min(a2, b2));
            a1 = m1; a2 = m2;
        }
        const int lt = trow0 + (r >> 1) * 16 + g + ((r & 1) ? 8 : 0);
        int winner;
        const float a1f = key2f(a1);
        const bool need = (key2f(a2) - a1f) < THETA;   // quad-uniform
        if (need) {
            const float cut = a1f + THETA;
            double bs = 1e300; int bi = 1 << 20;
            const uint32_t kr[3] = { k1[r], k2[r], k3[r] };
#pragma unroll
            for (int cc = 0; cc < 3; cc++) {
                if (key2f(kr[cc]) <= cut) {
                    const int idx = (int)(kr[cc] & 1023u);
                    const float4* er = (const float4*)(embed + (size_t)idx * DD);
                    double nrm = 0.0, dot = 0.0;
#pragma unroll
                    for (int i = 0; i < 16; i++) {
                        float4 v = __ldg(er + i);
                        double e0 = v.x, e1 = v.y, e2 = v.z, e3 = v.w;
                        nrm = fma(e0, e0, nrm); nrm = fma(e1, e1, nrm);
                        nrm = fma(e2, e2, nrm); nrm = fma(e3, e3, nrm);
                        dot = fma(e0, (double)Xs[(4*i+0) * MT_CTA + lt], dot);
                        dot = fma(e1, (double)Xs[(4*i+1) * MT_CTA + lt], dot);
                        dot = fma(e2, (double)Xs[(4*i+2) * MT_CTA + lt], dot);
                        dot = fma(e3, (double)Xs[(4*i+3) * MT_CTA + lt], dot);
                    }
                    double sc = nrm - 2.0 * dot;
                    if (sc < bs || (sc == bs && idx < bi)) { bs = sc; bi = idx; }
                }
            }
#pragma unroll
            for (int off = 1; off < 4; off <<= 1) {
                double os = __shfl_xor_sync(qmask, bs, off);
                int    oi = __shfl_xor_sync(qmask, bi, off);
                if (os < bs || (os == bs && oi < bi)) { bs = os; bi = oi; }
            }
            winner = bi;
        } else {
            winner = (int)(a1 & 1023u);
        }
        if (tig == 0) {
            Sidx[lt] = winner;
            out[IDX_OFF + (size_t)(base + lt)] = (float)winner;
        }
    }
    __syncthreads();

    // Epilogue: gather winner rows (reuse codebook smem), coalesced ST output.
    float* Eg = (float*)(smem + SM_ES);          // [256][65] floats
    {
        const int lt = tid;
        const int bi = Sidx[lt];
        const float4* er = (const float4*)(embed + (size_t)bi * DD);
#pragma unroll
        for (int i = 0; i < 16; i++) {
            float4 v = __ldg(er + i);
            Eg[lt * 65 + 4 * i + 0] = v.x; Eg[lt * 65 + 4 * i + 1] = v.y;
            Eg[lt * 65 + 4 * i + 2] = v.z; Eg[lt * 65 + 4 * i + 3] = v.w;
        }
    }
    __syncthreads();

    float lsum = 0.f;
    for (int i = tid; i < DD * MT_CTA; i += TPB) {
        const int d = i >> 8, t = i & 255;
        float xv = Xs[i];
        float diff = Eg[t * 65 + d] - xv;
        lsum = fmaf(diff, diff, lsum);
        out[(size_t)b * DD * HW + (size_t)d * HW + hw0 + t] = xv + diff;
    }
#pragma unroll
    for (int o = 16; o > 0; o >>= 1) lsum += __shfl_down_sync(0xFFFFFFFFu, lsum, o);
    if (lane == 0) Red[wid] = lsum;
    __syncthreads();
    if (wid == 0) {
        float v = (lane < TPB / 32) ? Red[lane] : 0.f;
#pragma unroll
        for (int o = 4; o > 0; o >>= 1) v += __shfl_down_sync(0xFFFFFFFFu, v, o);
        if (lane == 0) g_part[blockIdx.x] = v;    // no atomics: fixed slot
    }
}

// Sum the 512 per-CTA partials (deterministic order) and write the loss.
__global__ void vq_finalize_kernel(float* __restrict__ out) {
    __shared__ float red[8];
    const int tid = threadIdx.x, lane = tid & 31, wid = tid >> 5;
    float v = g_part[tid] + g_part[tid + 256];
#pragma unroll
    for (int o = 16; o > 0; o >>= 1) v += __shfl_down_sync(0xFFFFFFFFu, v, o);
    if (lane == 0) red[wid] = v;
    __syncthreads();
    if (wid == 0) {
        float s = (lane < 8) ? red[lane] : 0.f;
#pragma unroll
        for (int o = 4; o > 0; o >>= 1) s += __shfl_down_sync(0xFFFFFFFFu, s, o);
        if (lane == 0) out[LOSS_OFF] = s / (float)((size_t)NTOK * DD);
    }
}

extern "C" void kernel_launch(void* const* d_in, const int* in_sizes, int n_in,
                              void* d_out, int out_size) {
    const float* z_e   = (const float*)d_in[0];
    const float* embed = (const float*)d_in[1];
    float* out = (float*)d_out;

    cudaFuncSetAttribute(vq_main_kernel,
                         cudaFuncAttributeMaxDynamicSharedMemorySize, SMEM_TOTAL);
    vq_main_kernel<<<NCTA, TPB, SMEM_TOTAL>>>(z_e, embed, out);
    vq_finalize_kernel<<<1, 256>>>(out);
}

// round 9
// speedup vs baseline: 4.7537x; 1.1620x over previous
#include <cuda_runtime.h>
#include <cuda_fp16.h>
#include <cstdint>

// ---------------------------------------------------------------------------
// VectorQuantize forward: persistent fp16 mma.sync screen, codes split across
// warp halves, norm folded into MMA accumulator init (d-space keys), top-3
// candidates + 3+3 merge + pruned fp64 exact rescore of near-ties.
//
//   z_e   : [B=32, D=64, H=64, W=64] f32
//   embed : [K=1024, D=64] f32
// Output (f32): [0,8388608) z_q_st | [8388608] loss | [8388609,8519681) idx
//
// d = x.e - (||e||^2 + 1024)/2 is always negative -> raw fp32 bits are
// order-reversed (min-uint = max d = min distance). Low 10 key bits carry the
// code index (quantum <= 0.0625 in d-space, covered by THETA_D + rescore).
// ---------------------------------------------------------------------------

#define DD    64
#define HW    4096
#define NTOK  131072
#define KK    1024
#define TPB   256
#define MT    128                 // tokens per job
#define NJOBS (NTOK / MT)         // 1024
#define GRID  148                 // persistent CTAs (one per SM)

#define ZQ_ELEMS 8388608UL
#define LOSS_OFF 8388608UL
#define IDX_OFF  8388609UL

#define ESTRIDE 144               // codebook row stride (bytes)
#define SM_ES   0                           // fp16 codebook, 1024x144 = 147456
#define SM_EN   (KK * ESTRIDE)              // -(||e||^2+C)/2 fp32 [1024], 4096
#define SM_XS   (SM_EN + KK * 4)            // X fp32 [64][128], 32768
#define SM_EG   (SM_XS + DD * MT * 4)       // gathered rows [128][65], 33280
#define SM_TOP  (SM_EG + MT * 65 * 4)       // partner keys [128][4][3], 6144
#define SM_SIDX (SM_TOP + MT * 12 * 4)      // winner per token, 512
#define SM_RED  (SM_SIDX + MT * 4)          // loss reduction, 64
#define SMEM_TOTAL (SM_RED + 64)            // 224320 B

#define CPOS    1024.0f
#define THETA_D 0.15f             // d-space: quantum 0.0625 + 6*sigma + margin

__device__ float g_part[GRID];

// top-3 on uint keys (min-uint = best); lower index auto-wins quantized ties
__device__ __forceinline__ void upd3(uint32_t& k1, uint32_t& k2, uint32_t& k3,
                                     float d, uint32_t code) {
    uint32_t u = (__float_as_uint(d) & 0xFFFFFC00u) | code;   // 1 LOP3
    uint32_t t1 = min(k1, u);
    uint32_t h1 = max(k1, u);
    uint32_t t2 = min(k2, h1);
    uint32_t h2 = max(k2, h1);
    k3 = min(k3, h2);
    k2 = t2; k1 = t1;
}
__device__ __forceinline__ float key2f(uint32_t k) {
    return __uint_as_float(k & 0xFFFFFC00u);   // negative float d-hat
}

// ---------------------------------------------------------------------------
__global__ __launch_bounds__(TPB, 1)
void vq_main_kernel(const float* __restrict__ z_e,
                    const float* __restrict__ embed,
                    float* __restrict__ out) {
    extern __shared__ __align__(16) char smem[];
    float* en_s = (float*)(smem + SM_EN);
    float* Xs   = (float*)(smem + SM_XS);
    float* Eg   = (float*)(smem + SM_EG);
    uint32_t* Top = (uint32_t*)(smem + SM_TOP);
    int*   Sidx = (int*)(smem + SM_SIDX);
    float* Red  = (float*)(smem + SM_RED);

    const int tid = threadIdx.x, wid = tid >> 5, lane = tid & 31;
    const int g = lane >> 2, tig = lane & 3;
    const int halfbase = (wid >> 2) * 512;     // code half per warp group
    const int trow0 = (wid & 3) * 32;          // token group per warp

    // ---- Stage codebook ONCE per CTA: fp16, MMA-fragment-ordered rows ----
    // Row word order: [tig][half][kt] so each thread reads 2x LDS.128.
    for (int r = tid; r < KK; r += TPB) {
        const float4* row = (const float4*)(embed + (size_t)r * DD);
        char* dst = smem + SM_ES + r * ESTRIDE;
        float s = CPOS;
        uint32_t w[32];
#pragma unroll
        for (int i = 0; i < 16; i++) {
            float4 v = __ldg(row + i);
            s = fmaf(v.x, v.x, s); s = fmaf(v.y, v.y, s);
            s = fmaf(v.z, v.z, s); s = fmaf(v.w, v.w, s);
            __half2 h0 = __floats2half2_rn(v.x, v.y);
            __half2 h1 = __floats2half2_rn(v.z, v.w);
            w[2 * i]     = *(uint32_t*)&h0;
            w[2 * i + 1] = *(uint32_t*)&h1;
        }
#pragma unroll
        for (int tg = 0; tg < 4; tg++)
#pragma unroll
            for (int hf = 0; hf < 2; hf++) {
                uint4 q = make_uint4(w[tg + 4 * hf], w[8 + tg + 4 * hf],
                                     w[16 + tg + 4 * hf], w[24 + tg + 4 * hf]);
                *(uint4*)(dst + tg * 32 + hf * 16) = q;
            }
        en_s[r] = -(s) * 0.5f;     // -(||e||^2 + C)/2
    }

    float lacc = 0.f;              // per-thread loss partial across jobs

    for (int job = blockIdx.x; job < NJOBS; job += GRID) {
        const int base = job * MT;
        const int b = base >> 12, hw0 = base & 4095;
        const float* zbase = z_e + (size_t)b * DD * HW + hw0;
        __syncthreads();           // prior job done with Xs/Eg

        // ---- Stage X (coalesced): Xs[d][t] ----
        for (int i = tid; i < DD * MT; i += TPB)
            Xs[i] = zbase[(size_t)(i >> 7) * HW + (i & 127)];
        __syncthreads();

        // ---- Build fp16 A fragments (32 tokens per warp) ----
        uint32_t A[4][2][4];
#pragma unroll
        for (int kt = 0; kt < 4; kt++)
#pragma unroll
            for (int mt = 0; mt < 2; mt++) {
                const int ta = trow0 + mt * 16 + g, tb = ta + 8;
                const int c0 = kt * 16 + tig * 2;
#pragma unroll
                for (int h = 0; h < 2; h++) {
                    const int cc = c0 + h * 8;
                    __half2 pa = __floats2half2_rn(Xs[cc * MT + ta],
                                                   Xs[(cc + 1) * MT + ta]);
                    __half2 pb = __floats2half2_rn(Xs[cc * MT + tb],
                                                   Xs[(cc + 1) * MT + tb]);
                    A[kt][mt][2 * h]     = *(uint32_t*)&pa;
                    A[kt][mt][2 * h + 1] = *(uint32_t*)&pb;
                }
            }

        // ---- Screen: 64 n-tiles of 8 codes (this warp's half) ----
        uint32_t k1[4], k2[4], k3[4];
#pragma unroll
        for (int r = 0; r < 4; r++) { k1[r] = k2[r] = k3[r] = 0xFFFFFFFFu; }

        const char* brow = smem + SM_ES + (halfbase + g) * ESTRIDE + tig * 32;
        const float2* enp = (const float2*)(en_s + halfbase + tig * 2);
        uint32_t ncur = (uint32_t)(halfbase + tig * 2);

#pragma unroll 4
        for (int nt = 0; nt < 64; nt++) {
            const uint4 Bv0 = *(const uint4*)(brow);        // B0 kt0..3
            const uint4 Bv1 = *(const uint4*)(brow + 16);   // B1 kt0..3
            const float2 en2 = *enp;
#pragma unroll
            for (int mt = 0; mt < 2; mt++) {
                float d0 = en2.x, d1 = en2.y, d2 = en2.x, d3 = en2.y;
#define VQ_MMA(b0, b1, kt) \
                asm volatile( \
                    "mma.sync.aligned.m16n8k16.row.col.f32.f16.f16.f32 " \
                    "{%0,%1,%2,%3}, {%4,%5,%6,%7}, {%8,%9}, {%0,%1,%2,%3};" \
                    : "+f"(d0), "+f"(d1), "+f"(d2), "+f"(d3) \
                    : "r"(A[kt][mt][0]), "r"(A[kt][mt][1]), \
                      "r"(A[kt][mt][2]), "r"(A[kt][mt][3]), \
                      "r"(b0), "r"(b1))
                VQ_MMA(Bv0.x, Bv1.x, 0);
                VQ_MMA(Bv0.y, Bv1.y, 1);
                VQ_MMA(Bv0.z, Bv1.z, 2);
                VQ_MMA(Bv0.w, Bv1.w, 3);
#undef VQ_MMA
                upd3(k1[mt*2],   k2[mt*2],   k3[mt*2],   d0, ncur);
                upd3(k1[mt*2],   k2[mt*2],   k3[mt*2],   d1, ncur + 1);
                upd3(k1[mt*2+1], k2[mt*2+1], k3[mt*2+1], d2, ncur);
                upd3(k1[mt*2+1], k2[mt*2+1], k3[mt*2+1], d3, ncur + 1);
            }
            brow += 8 * ESTRIDE;
            enp  += 4;
            ncur += 8;
        }

        // ---- Cross-half merge: warps 4-7 publish, warps 0-3 resolve ----
        if (wid >= 4) {
#pragma unroll
            for (int r = 0; r < 4; r++) {
                const int lt = trow0 + (r >> 1) * 16 + g + ((r & 1) ? 8 : 0);
                Top[lt * 12 + tig * 3 + 0] = k1[r];
                Top[lt * 12 + tig * 3 + 1] = k2[r];
                Top[lt * 12 + tig * 3 + 2] = k3[r];
            }
        }
        __syncthreads();

        if (wid < 4) {
#pragma unroll
            for (int r = 0; r < 4; r++) {
                const int lt = trow0 + (r >> 1) * 16 + g + ((r & 1) ? 8 : 0);
                const uint32_t p1 = Top[lt * 12 + tig * 3 + 0];
                const uint32_t p2 = Top[lt * 12 + tig * 3 + 1];
                const uint32_t p3 = Top[lt * 12 + tig * 3 + 2];
                // merge sorted triples, keep top-3 of union
                uint32_t m1 = min(k1[r], p1);
                uint32_t x  = max(k1[r], p1);
                uint32_t mn = min(k2[r], p2);
                uint32_t mx = max(k2[r], p2);
                uint32_t m2 = min(x, mn);
                uint32_t y  = max(x, mn);
                uint32_t m3 = min(min(y, mx), min(k3[r], p3));

                // quad-merge top-2 for the gap test
                uint32_t a1 = m1, a2 = m2;
#pragma unroll
                for (int off = 1; off < 4; off <<= 1) {
                    uint32_t b1 = __shfl_xor_sync(0xFFFFFFFFu, a1, off);
                    uint32_t b2 = __shfl_xor_sync(0xFFFFFFFFu, a2, off);
                    uint32_t q1 = min(a1, b1);
                    uint32_t q2 = min(max(a1, b1), min(a2, b2));
                    a1 = q1; a2 = q2;
                }
                int winner;
                const float a1f = key2f(a1);
                const bool need = (a1f - key2f(a2)) < THETA_D;  // quad-uniform
                if (need) {
                    const float cut = a1f - THETA_D;
                    double bs = 1e300; int bi = 1 << 20;
                    const uint32_t kr[3] = { m1, m2, m3 };
#pragma unroll
                    for (int cc = 0; cc < 3; cc++) {
                        if (key2f(kr[cc]) >= cut) {
                            const int idx = (int)(kr[cc] & 1023u);
                            const float4* er = (const float4*)(embed + (size_t)idx * DD);
                            double nrm = 0.0, dot = 0.0;
#pragma unroll
                            for (int i = 0; i < 16; i++) {
                                float4 v = __ldg(er + i);
                                double e0 = v.x, e1 = v.y, e2 = v.z, e3 = v.w;
                                nrm = fma(e0, e0, nrm); nrm = fma(e1, e1, nrm);
                                nrm = fma(e2, e2, nrm); nrm = fma(e3, e3, nrm);
                                dot = fma(e0, (double)Xs[(4*i+0) * MT + lt], dot);
                                dot = fma(e1, (double)Xs[(4*i+1) * MT + lt], dot);
                                dot = fma(e2, (double)Xs[(4*i+2) * MT + lt], dot);
                                dot = fma(e3, (double)Xs[(4*i+3) * MT + lt], dot);
                            }
                            double sc = nrm - 2.0 * dot;
                            if (sc < bs || (sc == bs && idx < bi)) { bs = sc; bi = idx; }
                        }
                    }
                    const uint32_t qmask = 0xFu << (lane & 28);
#pragma unroll
                    for (int off = 1; off < 4; off <<= 1) {
                        double os = __shfl_xor_sync(qmask, bs, off);
                        int    oi = __shfl_xor_sync(qmask, bi, off);
                        if (os < bs || (os == bs && oi < bi)) { bs = os; bi = oi; }
                    }
                    winner = bi;
                } else {
                    winner = (int)(a1 & 1023u);
                }
                if (tig == 0) {
                    Sidx[lt] = winner;
                    out[IDX_OFF + (size_t)(base + lt)] = (float)winner;
                }
            }
        }
        __syncthreads();

        // ---- Epilogue: gather winner rows, straight-through write + loss ----
        if (tid < MT) {
            const int bi = Sidx[tid];
            const float4* er = (const float4*)(embed + (size_t)bi * DD);
#pragma unroll
            for (int i = 0; i < 16; i++) {
                float4 v = __ldg(er + i);
                Eg[tid * 65 + 4 * i + 0] = v.x; Eg[tid * 65 + 4 * i + 1] = v.y;
                Eg[tid * 65 + 4 * i + 2] = v.z; Eg[tid * 65 + 4 * i + 3] = v.w;
            }
        }
        __syncthreads();

        for (int i = tid; i < DD * MT; i += TPB) {
            const int d = i >> 7, t = i & 127;
            float xv = Xs[i];
            float diff = Eg[t * 65 + d] - xv;
            lacc = fmaf(diff, diff, lacc);
            out[(size_t)b * DD * HW + (size_t)d * HW + hw0 + t] = xv + diff;
        }
    }

    // ---- CTA loss partial (deterministic; no atomics) ----
#pragma unroll
    for (int o = 16; o > 0; o >>= 1) lacc += __shfl_down_sync(0xFFFFFFFFu, lacc, o);
    __syncthreads();
    if (lane == 0) Red[wid] = lacc;
    __syncthreads();
    if (wid == 0) {
        float v = (lane < TPB / 32) ? Red[lane] : 0.f;
#pragma unroll
        for (int o = 4; o > 0; o >>= 1) v += __shfl_down_sync(0xFFFFFFFFu, v, o);
        if (lane == 0) g_part[blockIdx.x] = v;
    }
}

// Sum the 148 per-CTA partials (deterministic order) and write the loss.
__global__ void vq_finalize_kernel(float* __restrict__ out) {
    __shared__ float red[8];
    const int tid = threadIdx.x, lane = tid & 31, wid = tid >> 5;
    float v = (tid < GRID) ? g_part[tid] : 0.f;
#pragma unroll
    for (int o = 16; o > 0; o >>= 1) v += __shfl_down_sync(0xFFFFFFFFu, v, o);
    if (lane == 0) red[wid] = v;
    __syncthreads();
    if (wid == 0) {
        float s = (lane < 8) ? red[lane] : 0.f;
#pragma unroll
        for (int o = 4; o > 0; o >>= 1) s += __shfl_down_sync(0xFFFFFFFFu, s, o);
        if (lane == 0) out[LOSS_OFF] = s / (float)((size_t)NTOK * DD);
    }
}

extern "C" void kernel_launch(void* const* d_in, const int* in_sizes, int n_in,
                              void* d_out, int out_size) {
    const float* z_e   = (const float*)d_in[0];
    const float* embed = (const float*)d_in[1];
    float* out = (float*)d_out;

    cudaFuncSetAttribute(vq_main_kernel,
                         cudaFuncAttributeMaxDynamicSharedMemorySize, SMEM_TOTAL);
    vq_main_kernel<<<GRID, TPB, SMEM_TOTAL>>>(z_e, embed, out);
    vq_finalize_kernel<<<1, 256>>>(out);
}

// round 12
// speedup vs baseline: 4.8021x; 1.0102x over previous
#include <cuda_runtime.h>
#include <cuda_fp16.h>
#include <cstdint>

// ---------------------------------------------------------------------------
// VectorQuantize forward: persistent fp16 mma.sync screen, codes split across
// warp halves, norm folded into MMA accumulator init (d-space keys), pair-
// merge top-3 tracking + 3+3 merge + pruned fp64 exact rescore of near-ties.
//
//   z_e   : [B=32, D=64, H=64, W=64] f32
//   embed : [K=1024, D=64] f32
// Output (f32): [0,8388608) z_q_st | [8388608] loss | [8388609,8519681) idx
//
// d = x.e - (||e||^2 + 1024)/2 is always negative -> raw fp32 bits are
// order-reversed (min-uint = best). Low 10 key bits carry the code index
// (quantum <= 0.0625 in d-space, covered by THETA_D + rescore).
// ---------------------------------------------------------------------------

#define DD    64
#define HW    4096
#define NTOK  131072
#define KK    1024
#define TPB   256
#define MT    128                 // tokens per job
#define NJOBS (NTOK / MT)         // 1024
#define GRID  148                 // persistent CTAs (one per SM)

#define ZQ_ELEMS 8388608UL
#define LOSS_OFF 8388608UL
#define IDX_OFF  8388609UL

#define ESTRIDE 144               // codebook row stride (bytes)
#define SM_ES   0                           // fp16 codebook, 1024x144 = 147456
#define SM_EN   (KK * ESTRIDE)              // -(||e||^2+C)/2 fp32 [1024], 4096
#define SM_XS   (SM_EN + KK * 4)            // X fp32 [64][128], 32768
#define SM_EG   (SM_XS + DD * MT * 4)       // gathered rows [128][65], 33280
#define SM_TOP  (SM_EG + MT * 65 * 4)       // partner keys [128][4][3], 6144
#define SM_SIDX (SM_TOP + MT * 12 * 4)      // winner per token, 512
#define SM_RED  (SM_SIDX + MT * 4)          // loss reduction, 64
#define SMEM_TOTAL (SM_RED + 64)            // 224320 B

#define CPOS    1024.0f
#define THETA_D 0.15f             // d-space: quantum 0.0625 + 6*sigma + margin

__device__ float g_part[GRID];

// Insert a fresh pair of scores into a sorted-3 (min-uint best) in 10 ops:
// 2 LOP3 key-forms + 8 IMNMX (merge sorted-2 into sorted-3, keep low 3).
__device__ __forceinline__ void upd_pair(uint32_t& k1, uint32_t& k2, uint32_t& k3,
                                         float d0, float d1, uint32_t n0) {
    uint32_t u0 = (__float_as_uint(d0) & 0xFFFFFC00u) | n0;
    uint32_t u1 = (__float_as_uint(d1) & 0xFFFFFC00u) | (n0 + 1u);
    uint32_t s1 = min(u0, u1);
    uint32_t s2 = max(u0, u1);
    uint32_t h  = max(k1, s1);
    k1 = min(k1, s1);
    uint32_t l2 = min(k2, s2);
    k2 = min(h, l2);
    k3 = min(k3, max(h, l2));
}
__device__ __forceinline__ float key2f(uint32_t k) {
    return __uint_as_float(k & 0xFFFFFC00u);   // negative float d-hat
}

// ---------------------------------------------------------------------------
__global__ __launch_bounds__(TPB, 1)
void vq_main_kernel(const float* __restrict__ z_e,
                    const float* __restrict__ embed,
                    float* __restrict__ out) {
    extern __shared__ __align__(16) char smem[];
    float* en_s = (float*)(smem + SM_EN);
    float* Xs   = (float*)(smem + SM_XS);
    float* Eg   = (float*)(smem + SM_EG);
    uint32_t* Top = (uint32_t*)(smem + SM_TOP);
    int*   Sidx = (int*)(smem + SM_SIDX);
    float* Red  = (float*)(smem + SM_RED);

    const int tid = threadIdx.x, wid = tid >> 5, lane = tid & 31;
    const int g = lane >> 2, tig = lane & 3;
    const int halfbase = (wid >> 2) * 512;     // code half per warp group
    const int trow0 = (wid & 3) * 32;          // token group per warp

    // ---- Stage codebook ONCE per CTA: fp16, MMA-fragment-ordered rows ----
    for (int r = tid; r < KK; r += TPB) {
        const float4* row = (const float4*)(embed + (size_t)r * DD);
        char* dst = smem + SM_ES + r * ESTRIDE;
        float s = CPOS;
        uint32_t w[32];
#pragma unroll
        for (int i = 0; i < 16; i++) {
            float4 v = __ldg(row + i);
            s = fmaf(v.x, v.x, s); s = fmaf(v.y, v.y, s);
            s = fmaf(v.z, v.z, s); s = fmaf(v.w, v.w, s);
            __half2 h0 = __floats2half2_rn(v.x, v.y);
            __half2 h1 = __floats2half2_rn(v.z, v.w);
            w[2 * i]     = *(uint32_t*)&h0;
            w[2 * i + 1] = *(uint32_t*)&h1;
        }
#pragma unroll
        for (int tg = 0; tg < 4; tg++)
#pragma unroll
            for (int hf = 0; hf < 2; hf++) {
                uint4 q = make_uint4(w[tg + 4 * hf], w[8 + tg + 4 * hf],
                                     w[16 + tg + 4 * hf], w[24 + tg + 4 * hf]);
                *(uint4*)(dst + tg * 32 + hf * 16) = q;
            }
        en_s[r] = -(s) * 0.5f;     // -(||e||^2 + C)/2
    }

    float lacc = 0.f;              // per-thread loss partial across jobs

    for (int job = blockIdx.x; job < NJOBS; job += GRID) {
        const int base = job * MT;
        const int b = base >> 12, hw0 = base & 4095;
        const float* zbase = z_e + (size_t)b * DD * HW + hw0;
        __syncthreads();           // prior job done with Xs/Eg

        // ---- Stage X (coalesced): Xs[d][t] ----
        for (int i = tid; i < DD * MT; i += TPB)
            Xs[i] = zbase[(size_t)(i >> 7) * HW + (i & 127)];
        __syncthreads();

        // ---- Build fp16 A fragments (32 tokens per warp) ----
        uint32_t A[4][2][4];
#pragma unroll
        for (int kt = 0; kt < 4; kt++)
#pragma unroll
            for (int mt = 0; mt < 2; mt++) {
                const int ta = trow0 + mt * 16 + g, tb = ta + 8;
                const int c0 = kt * 16 + tig * 2;
#pragma unroll
                for (int h = 0; h < 2; h++) {
                    const int cc = c0 + h * 8;
                    __half2 pa = __floats2half2_rn(Xs[cc * MT + ta],
                                                   Xs[(cc + 1) * MT + ta]);
                    __half2 pb = __floats2half2_rn(Xs[cc * MT + tb],
                                                   Xs[(cc + 1) * MT + tb]);
                    A[kt][mt][2 * h]     = *(uint32_t*)&pa;
                    A[kt][mt][2 * h + 1] = *(uint32_t*)&pb;
                }
            }

        // ---- Screen: 64 n-tiles of 8 codes (this warp's half) ----
        uint32_t k1[4], k2[4], k3[4];
#pragma unroll
        for (int r = 0; r < 4; r++) { k1[r] = k2[r] = k3[r] = 0xFFFFFFFFu; }

        const char* brow = smem + SM_ES + (halfbase + g) * ESTRIDE + tig * 32;
        const float2* enp = (const float2*)(en_s + halfbase + tig * 2);
        uint32_t ncur = (uint32_t)(halfbase + tig * 2);

#pragma unroll 4
        for (int nt = 0; nt < 64; nt++) {
            const uint4 Bv0 = *(const uint4*)(brow);        // B0 kt0..3
            const uint4 Bv1 = *(const uint4*)(brow + 16);   // B1 kt0..3
            const float2 en2 = *enp;
#pragma unroll
            for (int mt = 0; mt < 2; mt++) {
                float d0 = en2.x, d1 = en2.y, d2 = en2.x, d3 = en2.y;
#define VQ_MMA(b0, b1, kt) \
                asm volatile( \
                    "mma.sync.aligned.m16n8k16.row.col.f32.f16.f16.f32 " \
                    "{%0,%1,%2,%3}, {%4,%5,%6,%7}, {%8,%9}, {%0,%1,%2,%3};" \
                    : "+f"(d0), "+f"(d1), "+f"(d2), "+f"(d3) \
                    : "r"(A[kt][mt][0]), "r"(A[kt][mt][1]), \
                      "r"(A[kt][mt][2]), "r"(A[kt][mt][3]), \
                      "r"(b0), "r"(b1))
                VQ_MMA(Bv0.x, Bv1.x, 0);
                VQ_MMA(Bv0.y, Bv1.y, 1);
                VQ_MMA(Bv0.z, Bv1.z, 2);
                VQ_MMA(Bv0.w, Bv1.w, 3);
#undef VQ_MMA
                upd_pair(k1[mt*2],   k2[mt*2],   k3[mt*2],   d0, d1, ncur);
                upd_pair(k1[mt*2+1], k2[mt*2+1], k3[mt*2+1], d2, d3, ncur);
            }
            brow += 8 * ESTRIDE;
            enp  += 4;
            ncur += 8;
        }

        // ---- Cross-half merge: warps 4-7 publish, warps 0-3 resolve ----
        if (wid >= 4) {
#pragma unroll
            for (int r = 0; r < 4; r++) {
                const int lt = trow0 + (r >> 1) * 16 + g + ((r & 1) ? 8 : 0);
                Top[lt * 12 + tig * 3 + 0] = k1[r];
                Top[lt * 12 + tig * 3 + 1] = k2[r];
                Top[lt * 12 + tig * 3 + 2] = k3[r];
            }
        }
        __syncthreads();

        if (wid < 4) {
#pragma unroll
            for (int r = 0; r < 4; r++) {
                const int lt = trow0 + (r >> 1) * 16 + g + ((r & 1) ? 8 : 0);
                const uint32_t p1 = Top[lt * 12 + tig * 3 + 0];
                const uint32_t p2 = Top[lt * 12 + tig * 3 + 1];
                const uint32_t p3 = Top[lt * 12 + tig * 3 + 2];
                // merge sorted triples, keep top-3 of union
                uint32_t m1 = min(k1[r], p1);
                uint32_t x  = max(k1[r], p1);
                uint32_t mn = min(k2[r], p2);
                uint32_t mx = max(k2[r], p2);
                uint32_t m2 = min(x, mn);
                uint32_t y  = max(x, mn);
                uint32_t m3 = min(min(y, mx), min(k3[r], p3));

                // quad-merge top-2 for the gap test
                uint32_t a1 = m1, a2 = m2;
#pragma unroll
                for (int off = 1; off < 4; off <<= 1) {
                    uint32_t b1 = __shfl_xor_sync(0xFFFFFFFFu, a1, off);
                    uint32_t b2 = __shfl_xor_sync(0xFFFFFFFFu, a2, off);
                    uint32_t q1 = min(a1, b1);
                    uint32_t q2 = min(max(a1, b1), min(a2, b2));
                    a1 = q1; a2 = q2;
                }
                int winner;
                const float a1f = key2f(a1);
                const bool need = (a1f - key2f(a2)) < THETA_D;  // quad-uniform
                if (need) {
                    const float cut = a1f - THETA_D;
                    double bs = 1e300; int bi = 1 << 20;
                    const uint32_t kr[3] = { m1, m2, m3 };
#pragma unroll
                    for (int cc = 0; cc < 3; cc++) {
                        if (key2f(kr[cc]) >= cut) {
                            const int idx = (int)(kr[cc] & 1023u);
                            const float4* er = (const float4*)(embed + (size_t)idx * DD);
                            double nrm = 0.0, dot = 0.0;
#pragma unroll
                            for (int i = 0; i < 16; i++) {
                                float4 v = __ldg(er + i);
                                double e0 = v.x, e1 = v.y, e2 = v.z, e3 = v.w;
                                nrm = fma(e0, e0, nrm); nrm = fma(e1, e1, nrm);
                                nrm = fma(e2, e2, nrm); nrm = fma(e3, e3, nrm);
                                dot = fma(e0, (double)Xs[(4*i+0) * MT + lt], dot);
                                dot = fma(e1, (double)Xs[(4*i+1) * MT + lt], dot);
                                dot = fma(e2, (double)Xs[(4*i+2) * MT + lt], dot);
                                dot = fma(e3, (double)Xs[(4*i+3) * MT + lt], dot);
                            }
                            double sc = nrm - 2.0 * dot;
                            if (sc < bs || (sc == bs && idx < bi)) { bs = sc; bi = idx; }
                        }
                    }
                    const uint32_t qmask = 0xFu << (lane & 28);
#pragma unroll
                    for (int off = 1; off < 4; off <<= 1) {
                        double os = __shfl_xor_sync(qmask, bs, off);
                        int    oi = __shfl_xor_sync(qmask, bi, off);
                        if (os < bs || (os == bs && oi < bi)) { bs = os; bi = oi; }
                    }
                    winner = bi;
                } else {
                    winner = (int)(a1 & 1023u);
                }
                if (tig == 0) {
                    Sidx[lt] = winner;
                    out[IDX_OFF + (size_t)(base + lt)] = (float)winner;
                }
            }
        }
        __syncthreads();

        // ---- Epilogue: gather (2 threads/row), float2 straight-through ----
        {
            const int t = tid >> 1, hf = tid & 1;
            const int bi = Sidx[t];
            const float4* er = (const float4*)(embed + (size_t)bi * DD) + hf * 8;
#pragma unroll
            for (int i = 0; i < 8; i++) {
                float4 v = __ldg(er + i);
                float* eg = Eg + t * 65 + hf * 32 + 4 * i;
                eg[0] = v.x; eg[1] = v.y; eg[2] = v.z; eg[3] = v.w;
            }
        }
        __syncthreads();

        for (int i = tid; i < DD * MT / 2; i += TPB) {
            const int d = i >> 6, t2 = (i & 63) * 2;
            float2 xv = *(const float2*)(Xs + d * MT + t2);
            float df0 = Eg[t2 * 65 + d] - xv.x;
            float df1 = Eg[(t2 + 1) * 65 + d] - xv.y;
            lacc = fmaf(df0, df0, lacc);
            lacc = fmaf(df1, df1, lacc);
            float2 o2 = make_float2(xv.x + df0, xv.y + df1);
            *(float2*)(out + (size_t)b * DD * HW + (size_t)d * HW + hw0 + t2) = o2;
        }
    }

    // ---- CTA loss partial (deterministic; no atomics) ----
#pragma unroll
    for (int o = 16; o > 0; o >>= 1) lacc += __shfl_down_sync(0xFFFFFFFFu, lacc, o);
    __syncthreads();
    if (lane == 0) Red[wid] = lacc;
    __syncthreads();
    if (wid == 0) {
        float v = (lane < TPB / 32) ? Red[lane] : 0.f;
#pragma unroll
        for (int o = 4; o > 0; o >>= 1) v += __shfl_down_sync(0xFFFFFFFFu, v, o);
        if (lane == 0) g_part[blockIdx.x] = v;
    }
}

// Sum the 148 per-CTA partials (deterministic order) and write the loss.
__global__ void vq_finalize_kernel(float* __restrict__ out) {
    __shared__ float red[8];
    const int tid = threadIdx.x, lane = tid & 31, wid = tid >> 5;
    float v = (tid < GRID) ? g_part[tid] : 0.f;
#pragma unroll
    for (int o = 16; o > 0; o >>= 1) v += __shfl_down_sync(0xFFFFFFFFu, v, o);
    if (lane == 0) red[wid] = v;
    __syncthreads();
    if (wid == 0) {
        float s = (lane < 8) ? red[lane] : 0.f;
#pragma unroll
        for (int o = 4; o > 0; o >>= 1) s += __shfl_down_sync(0xFFFFFFFFu, s, o);
        if (lane == 0) out[LOSS_OFF] = s / (float)((size_t)NTOK * DD);
    }
}

extern "C" void kernel_launch(void* const* d_in, const int* in_sizes, int n_in,
                              void* d_out, int out_size) {
    const float* z_e   = (const float*)d_in[0];
    const float* embed = (const float*)d_in[1];
    float* out = (float*)d_out;

    cudaFuncSetAttribute(vq_main_kernel,
                         cudaFuncAttributeMaxDynamicSharedMemorySize, SMEM_TOTAL);
    vq_main_kernel<<<GRID, TPB, SMEM_TOTAL>>>(z_e, embed, out);
    vq_finalize_kernel<<<1, 256>>>(out);
}